// round 14
// baseline (speedup 1.0000x reference)
#include <cuda_runtime.h>
#include <cstdint>

#define SLEN 1024
#define BSZ  16
#define IND  256
#define NH   8
#define DH   32
#define PROJ 776              // NH*(3*DH+1)
#define NTOK (SLEN*BSZ)       // 16384
#define NCHAIN (BSZ*NH)       // 128
#define FW_ELEMS (NCHAIN*DH*DH)
#define TCH  32               // staged steps per refill (4 chunks of 8)
#define CH8  8                // WY chunk size
#define NCH8 (SLEN/CH8)       // 128 chunks per chain
#define RTOT (PROJ*IND + IND*IND)   // 264192 weight elems to round

// Scratch (static device globals; no runtime allocation)
__device__ __align__(16) float g_normed[(size_t)NTOK*IND];   // tf32-rounded
__device__ __align__(16) float g_qkvb[(size_t)NTOK*PROJ];
__device__ __align__(16) float g_oseq[(size_t)NTOK*IND];     // tf32-rounded
__device__ __align__(16) float g_kn[(size_t)NCHAIN*SLEN*DH];
__device__ __align__(16) float g_qn[(size_t)NCHAIN*SLEN*DH];
__device__ __align__(16) float g_bv[(size_t)NCHAIN*SLEN*DH];  // beta*v
__device__ __align__(16) float g_nb[(size_t)NCHAIN*SLEN];     // -beta
__device__ __align__(16) float g_cross[(size_t)NCHAIN*NCH8*64];
__device__ __align__(16) float g_wslow_t[(size_t)PROJ*IND];  // tf32-rounded
__device__ __align__(16) float g_wout_t[(size_t)IND*IND];    // tf32-rounded

// ---------------------------------------------------------------------------
// helpers
// ---------------------------------------------------------------------------
typedef unsigned long long u64t;

__device__ __forceinline__ u64t f2pack(float lo, float hi) {
    u64t r; asm("mov.b64 %0, {%1, %2};" : "=l"(r) : "f"(lo), "f"(hi)); return r;
}
__device__ __forceinline__ void f2unpack(u64t v, float& lo, float& hi) {
    asm("mov.b64 {%0, %1}, %2;" : "=f"(lo), "=f"(hi) : "l"(v));
}
__device__ __forceinline__ u64t ffma2(u64t a, u64t b, u64t c) {
    u64t d; asm("fma.rn.f32x2 %0, %1, %2, %3;" : "=l"(d) : "l"(a), "l"(b), "l"(c)); return d;
}
__device__ __forceinline__ uint32_t to_tf32(float x) {
    uint32_t u; asm("cvt.rna.tf32.f32 %0, %1;" : "=r"(u) : "f"(x)); return u;
}
__device__ __forceinline__ float rnd_tf32(float x) {
    return __uint_as_float(to_tf32(x));
}
__device__ __forceinline__ uint32_t smem_u32(const void* p) {
    return (uint32_t)__cvta_generic_to_shared(p);
}
__device__ __forceinline__ void cp16(uint32_t d, const void* s, int ssz) {
    asm volatile("cp.async.ca.shared.global [%0], [%1], 16, %2;" :: "r"(d), "l"(s), "r"(ssz));
}
__device__ __forceinline__ void cp_commit() { asm volatile("cp.async.commit_group;" ::); }
__device__ __forceinline__ void cp_wait0()  { asm volatile("cp.async.wait_group 0;" ::); }

// upper-tri (i<=j) and strict (i<j) index maps over 8 steps
__host__ __device__ constexpr int UTx(int i, int j) { return i * (15 - i) / 2 + j; }
__host__ __device__ constexpr int STx(int i, int j) { return i * (13 - i) / 2 + j - 1; }

// ---------------------------------------------------------------------------
// LN: one WARP per row (2x float4 per thread, shuffle-only) + weight rounding
// ---------------------------------------------------------------------------
__global__ __launch_bounds__(256)
void ln_round_kernel(const float* __restrict__ x,
                     const float* __restrict__ gamma,
                     const float* __restrict__ beta,
                     const float* __restrict__ Wslow,
                     const float* __restrict__ Wout)
{
    int blk = blockIdx.x, tid = threadIdx.x;
    if (blk >= NTOK / 8) {
        int i = (blk - NTOK / 8) * 256 + tid;
        if (i < PROJ * IND)       g_wslow_t[i] = rnd_tf32(Wslow[i]);
        else if (i < RTOT)        g_wout_t[i - PROJ * IND] = rnd_tf32(Wout[i - PROJ * IND]);
        return;
    }
    int wid = tid >> 5, lane = tid & 31;
    int row = blk * 8 + wid;
    const float4* xr = (const float4*)(x + (size_t)row * IND);
    float4 a = xr[lane * 2], b2 = xr[lane * 2 + 1];
    float s  = (a.x + a.y + a.z + a.w) + (b2.x + b2.y + b2.z + b2.w);
    float s2 = (a.x*a.x + a.y*a.y + a.z*a.z + a.w*a.w) +
               (b2.x*b2.x + b2.y*b2.y + b2.z*b2.z + b2.w*b2.w);
#pragma unroll
    for (int o = 16; o > 0; o >>= 1) {
        s  += __shfl_xor_sync(0xffffffffu, s,  o);
        s2 += __shfl_xor_sync(0xffffffffu, s2, o);
    }
    float mu  = s * (1.0f / IND);
    float var = s2 * (1.0f / IND) - mu * mu;
    float rr  = rsqrtf(var + 1e-5f);
    float4 ga = ((const float4*)gamma)[lane * 2], gb = ((const float4*)gamma)[lane * 2 + 1];
    float4 ba = ((const float4*)beta)[lane * 2],  bb = ((const float4*)beta)[lane * 2 + 1];
    float4 o0, o1;
    o0.x = rnd_tf32((a.x - mu) * rr * ga.x + ba.x);
    o0.y = rnd_tf32((a.y - mu) * rr * ga.y + ba.y);
    o0.z = rnd_tf32((a.z - mu) * rr * ga.z + ba.z);
    o0.w = rnd_tf32((a.w - mu) * rr * ga.w + ba.w);
    o1.x = rnd_tf32((b2.x - mu) * rr * gb.x + bb.x);
    o1.y = rnd_tf32((b2.y - mu) * rr * gb.y + bb.y);
    o1.z = rnd_tf32((b2.z - mu) * rr * gb.z + bb.z);
    o1.w = rnd_tf32((b2.w - mu) * rr * gb.w + bb.w);
    float4* orow = (float4*)(g_normed + (size_t)row * IND);
    orow[lane * 2]     = o0;
    orow[lane * 2 + 1] = o1;
}

// ---------------------------------------------------------------------------
// TF32 tensor-core GEMM, cp.async streamed. Block 128x128, 4 warps (2x2),
// warp tile 64x64 (mf=4, nf=8) -> 128 smem-bytes per MMA.
// ---------------------------------------------------------------------------
#define TBM 128
#define TBN 128
#define TBK 16
#define TPAD 20

__global__ __launch_bounds__(128)
void gemm_tf32(const float* __restrict__ A, const float* __restrict__ B,
               float* __restrict__ C, int M, int N, int K,
               const float* __restrict__ resid)
{
    __shared__ uint32_t As[2][TBM][TPAD];
    __shared__ uint32_t Bs[2][TBN][TPAD];

    int bm = blockIdx.x * TBM;
    int bn = blockIdx.y * TBN;
    int tid = threadIdx.x;
    int wid = tid >> 5, lane = tid & 31;
    int warpM = wid & 1, warpN = wid >> 1;        // 2 x 2 warp grid
    int gID = lane >> 2, tIG = lane & 3;
    int wm0 = warpM * 64, wn0 = warpN * 64;

    // staging: 4 cp16 per operand per thread
    int rr[4], kc[4], bz[4];
    uint32_t aA[2][4], aB[2][4];
#pragma unroll
    for (int i = 0; i < 4; i++) {
        int f = tid + i * 128;
        rr[i] = f >> 2; kc[i] = (f & 3) * 4;
        bz[i] = (bn + rr[i] < N) ? 16 : 0;
#pragma unroll
        for (int bf = 0; bf < 2; bf++) {
            aA[bf][i] = smem_u32(&As[bf][rr[i]][kc[i]]);
            aB[bf][i] = smem_u32(&Bs[bf][rr[i]][kc[i]]);
        }
    }

    auto LOADA = [&](int k0, int bf) {
#pragma unroll
        for (int i = 0; i < 4; i++) {
            cp16(aA[bf][i], A + (size_t)(bm + rr[i]) * K + k0 + kc[i], 16);
            cp16(aB[bf][i], B + (size_t)(bn + rr[i]) * K + k0 + kc[i], bz[i]);
        }
        cp_commit();
    };

    float acc[4][8][4];
#pragma unroll
    for (int i = 0; i < 4; i++)
#pragma unroll
        for (int j = 0; j < 8; j++)
#pragma unroll
            for (int c = 0; c < 4; c++) acc[i][j][c] = 0.f;

    LOADA(0, 0);

    int nk = K / TBK;
    for (int kt = 0; kt < nk; kt++) {
        int cur = kt & 1;
        cp_wait0();
        __syncthreads();
        if (kt + 1 < nk) LOADA((kt + 1) * TBK, cur ^ 1);

#pragma unroll
        for (int k8 = 0; k8 < TBK; k8 += 8) {
            uint32_t af[4][4];
#pragma unroll
            for (int mf = 0; mf < 4; mf++) {
                int row = wm0 + mf * 16 + gID;
                af[mf][0] = As[cur][row][k8 + tIG];
                af[mf][1] = As[cur][row + 8][k8 + tIG];
                af[mf][2] = As[cur][row][k8 + tIG + 4];
                af[mf][3] = As[cur][row + 8][k8 + tIG + 4];
            }
#pragma unroll
            for (int nf = 0; nf < 8; nf++) {
                int col = wn0 + nf * 8 + gID;
                uint32_t b0 = Bs[cur][col][k8 + tIG];
                uint32_t b1 = Bs[cur][col][k8 + tIG + 4];
#pragma unroll
                for (int mf = 0; mf < 4; mf++) {
                    asm volatile(
                        "mma.sync.aligned.m16n8k8.row.col.f32.tf32.tf32.f32 "
                        "{%0,%1,%2,%3}, {%4,%5,%6,%7}, {%8,%9}, {%0,%1,%2,%3};"
                        : "+f"(acc[mf][nf][0]), "+f"(acc[mf][nf][1]),
                          "+f"(acc[mf][nf][2]), "+f"(acc[mf][nf][3])
                        : "r"(af[mf][0]), "r"(af[mf][1]), "r"(af[mf][2]), "r"(af[mf][3]),
                          "r"(b0), "r"(b1));
                }
            }
        }
    }

#pragma unroll
    for (int mf = 0; mf < 4; mf++) {
#pragma unroll
        for (int nf = 0; nf < 8; nf++) {
            int m = bm + wm0 + mf * 16 + gID;
            int n = bn + wn0 + nf * 8 + 2 * tIG;
            if (n < N) {
                float c0 = acc[mf][nf][0], c1 = acc[mf][nf][1];
                float c2 = acc[mf][nf][2], c3 = acc[mf][nf][3];
                if (resid) {
                    float2 ra = *(const float2*)(resid + (size_t)m * N + n);
                    float2 rb = *(const float2*)(resid + (size_t)(m + 8) * N + n);
                    c0 += ra.x; c1 += ra.y; c2 += rb.x; c3 += rb.y;
                }
                *(float2*)(C + (size_t)m * N + n)       = make_float2(c0, c1);
                *(float2*)(C + (size_t)(m + 8) * N + n) = make_float2(c2, c3);
            }
        }
    }
}

// ---------------------------------------------------------------------------
// Fused prep, 8-step chunks: one warp per (chain, chunk).
// Streams out: kn, qn (normalized), bv = beta*v, nb = -beta, cross terms.
// cross layout per chunk: [0..35] kq(i<=j), [36..63] -b_j*kk(i<j)
// ---------------------------------------------------------------------------
__global__ __launch_bounds__(128)
void prep_fused()
{
    int gw   = blockIdx.x * 4 + (threadIdx.x >> 5);   // 0 .. NCHAIN*NCH8-1
    int lane = threadIdx.x & 31;
    int ch   = gw >> 7;          // chain  (NCH8 = 128)
    int cu   = gw & 127;         // chunk
    int t0   = cu * CH8;
    int b    = ch >> 3, h = ch & 7;

    float eq[8], ek[8], vv[8], be[8];
#pragma unroll
    for (int s = 0; s < 8; s++) {
        const float* base = g_qkvb + ((size_t)(t0 + s) * BSZ + b) * PROJ + h * 97;
        float q = base[lane], k = base[32 + lane];
        vv[s]  = base[64 + lane];
        be[s]  = 1.0f / (1.0f + __expf(-base[96]));
        eq[s] = q > 0.f ? q + 1.f : __expf(q);
        ek[s] = k > 0.f ? k + 1.f : __expf(k);
    }

    float r[80];
#pragma unroll
    for (int s = 0; s < 8; s++) { r[s] = eq[s]; r[8 + s] = ek[s]; }
#pragma unroll
    for (int i = 0; i < 8; i++)
#pragma unroll
        for (int j = 0; j < 8; j++)
            if (j >= i) r[16 + UTx(i, j)] = ek[i] * eq[j];
#pragma unroll
    for (int i = 0; i < 8; i++)
#pragma unroll
        for (int j = 0; j < 8; j++)
            if (j > i) r[52 + STx(i, j)] = ek[i] * ek[j];

#pragma unroll
    for (int o = 16; o > 0; o >>= 1) {
#pragma unroll
        for (int i = 0; i < 80; i++)
            r[i] += __shfl_xor_sync(0xffffffffu, r[i], o);
    }

    float rsq[8], rsk[8];
#pragma unroll
    for (int s = 0; s < 8; s++) {
        rsq[s] = 1.0f / (r[s] + 1e-5f);
        rsk[s] = 1.0f / (r[8 + s] + 1e-5f);
    }

#pragma unroll
    for (int s = 0; s < 8; s++) {
        size_t oi = ((size_t)ch * SLEN + t0 + s) * DH + lane;
        g_qn[oi] = eq[s] * rsq[s];
        g_kn[oi] = ek[s] * rsk[s];
        g_bv[oi] = be[s] * vv[s];
    }

#pragma unroll
    for (int i = 0; i < 8; i++)
#pragma unroll
        for (int j = 0; j < 8; j++)
            if (j >= i) r[16 + UTx(i, j)] *= rsk[i] * rsq[j];
#pragma unroll
    for (int i = 0; i < 8; i++)
#pragma unroll
        for (int j = 0; j < 8; j++)
            if (j > i) r[52 + STx(i, j)] *= -be[j] * rsk[i] * rsk[j];

    if (lane == 0) {
        size_t bb = (size_t)ch * SLEN + t0;
#pragma unroll
        for (int s = 0; s < 8; s++) g_nb[bb + s] = -be[s];
        float4* o = (float4*)(g_cross + ((size_t)ch * NCH8 + cu) * 64);
#pragma unroll
        for (int u = 0; u < 16; u++)
            o[u] = make_float4(r[16 + 4 * u], r[17 + 4 * u], r[18 + 4 * u], r[19 + 4 * u]);
    }
}

// ---------------------------------------------------------------------------
// Delta-rule recurrence: 2 CHAINS PER BLOCK (512 threads), WY chunk = 8,
// 8 warps per chain. Warp w of a chain: col-group g = w&3, role = w>>2.
// Dynamic smem (two chains' buffers). One barrier per 8-step chunk.
// ---------------------------------------------------------------------------
struct RecSmem {
    float sk[2][2][TCH * DH];     // [cs][buf]
    float sq[2][2][TCH * DH];
    float sbv[2][2][TCH * DH];
    float snb[2][2][TCH];
    float scr[2][2][256];         // 4 chunks x 64
    float part[2][2][16][32][4];  // [cs][pc][s][row][g]
};

__global__ __launch_bounds__(512)
void rec_kernel(const float* __restrict__ state,
                float* __restrict__ out_fw, int write_fw)
{
    extern __shared__ __align__(16) char smem_raw[];
    RecSmem* S = (RecSmem*)smem_raw;

    int tid  = threadIdx.x;
    int cs   = tid >> 8;               // chain slot 0/1
    int ctid = tid & 255;
    int chain = blockIdx.x * 2 + cs;   // 0..127
    int b = chain >> 3, h = chain & 7;
    int r = ctid & 31;                 // row
    int w = ctid >> 5;                 // warp-in-chain 0..7
    int g = w & 3;                     // column group
    int isQ = w >> 2;                  // role

    u64t Wp[4];
    const u64t* st = (const u64t*)(state + ((size_t)chain * DH + r) * DH + g * 8);
#pragma unroll
    for (int j = 0; j < 4; j++) Wp[j] = st[j];

    const float* kb  = g_kn + (size_t)chain * SLEN * DH;
    const float* qb  = g_qn + (size_t)chain * SLEN * DH;
    const float* vb  = g_bv + (size_t)chain * SLEN * DH;
    const float* nbb = g_nb + (size_t)chain * SLEN;
    const float* crb = g_cross + (size_t)chain * NCH8 * 64;

    auto REFILL = [&](int cc, int buf) {
        ((float4*)S->sk[cs][buf])[ctid]  = ((const float4*)(kb + (size_t)cc * TCH * DH))[ctid];
        ((float4*)S->sq[cs][buf])[ctid]  = ((const float4*)(qb + (size_t)cc * TCH * DH))[ctid];
        ((float4*)S->sbv[cs][buf])[ctid] = ((const float4*)(vb + (size_t)cc * TCH * DH))[ctid];
        if (ctid < TCH) S->snb[cs][buf][ctid] = nbb[cc * TCH + ctid];
        S->scr[cs][buf][ctid] = crb[(size_t)cc * 256 + ctid];
    };

    REFILL(0, 0);
    __syncthreads();

    const int NCC = SLEN / TCH;     // 32 refills, 4 chunks each
    for (int cc = 0; cc < NCC; cc++) {
        int buf = cc & 1;
        if (cc + 1 < NCC) REFILL(cc + 1, buf ^ 1);

#pragma unroll
        for (int sub = 0; sub < TCH / CH8; sub++) {
            int tb = sub * CH8;
            int pc = sub & 1;

            const float* srcb = isQ ? &S->sq[cs][buf][0] : &S->sk[cs][buf][0];
            u64t ks[8][4];
#pragma unroll
            for (int s = 0; s < 8; s++) {
                const float4* vp4 = (const float4*)&srcb[(tb + s) * DH + g * 8];
                float4 t0 = vp4[0], t1 = vp4[1];
                u64t v0 = f2pack(t0.x, t0.y), v1 = f2pack(t0.z, t0.w);
                u64t v2 = f2pack(t1.x, t1.y), v3 = f2pack(t1.z, t1.w);
                if (!isQ) { ks[s][0] = v0; ks[s][1] = v1; ks[s][2] = v2; ks[s][3] = v3; }
                u64t aa = ffma2(Wp[0], v0, 0ull), bb2 = ffma2(Wp[1], v1, 0ull);
                aa = ffma2(Wp[2], v2, aa); bb2 = ffma2(Wp[3], v3, bb2);
                float x0, x1, y0, y1;
                f2unpack(aa, x0, x1); f2unpack(bb2, y0, y1);
                S->part[cs][pc][isQ * 8 + s][r][g] = (x0 + y0) + (x1 + y1);
            }
            __syncthreads();

            float A[8];
#pragma unroll
            for (int s = 0; s < 8; s++) {
                float4 pa = *(const float4*)S->part[cs][pc][s][r];
                A[s] = (pa.x + pa.y) + (pa.z + pa.w);
            }

            const float* cq = &S->scr[cs][buf][sub * 64];
            const float* ck = cq + 36;

            float acc[8];
#pragma unroll
            for (int j = 0; j < 8; j++)
                acc[j] = fmaf(S->snb[cs][buf][tb + j], A[j],
                              S->sbv[cs][buf][(tb + j) * DH + r]);
            float d[8];
#pragma unroll
            for (int i = 0; i < 8; i++) {
                d[i] = acc[i];
#pragma unroll
                for (int j = 0; j < 8; j++)
                    if (j > i) acc[j] = fmaf(d[i], ck[STx(i, j)], acc[j]);
            }

            // output: warp w emits step w
            float4 pq = *(const float4*)S->part[cs][pc][8 + w][r];
            float Qw = (pq.x + pq.y) + (pq.z + pq.w);
#pragma unroll
            for (int i = 0; i < 8; i++)
                if (i <= w) Qw = fmaf(d[i], cq[UTx(i, w)], Qw);
            int tg = cc * TCH + tb;
            g_oseq[((size_t)(tg + w) * BSZ + b) * IND + h * DH + r] = rnd_tf32(Qw);

            // rank-8 update
            if (!isQ) {
#pragma unroll
                for (int s = 0; s < 8; s++) {
                    u64t D = f2pack(d[s], d[s]);
#pragma unroll
                    for (int j = 0; j < 4; j++) Wp[j] = ffma2(D, ks[s][j], Wp[j]);
                }
            } else {
#pragma unroll
                for (int s = 0; s < 8; s++) {
                    const float4* kp4 = (const float4*)&S->sk[cs][buf][(tb + s) * DH + g * 8];
                    float4 t0 = kp4[0], t1 = kp4[1];
                    u64t D = f2pack(d[s], d[s]);
                    Wp[0] = ffma2(D, f2pack(t0.x, t0.y), Wp[0]);
                    Wp[1] = ffma2(D, f2pack(t0.z, t0.w), Wp[1]);
                    Wp[2] = ffma2(D, f2pack(t1.x, t1.y), Wp[2]);
                    Wp[3] = ffma2(D, f2pack(t1.z, t1.w), Wp[3]);
                }
            }
        }
        __syncthreads();   // close refill window for buf
    }

    if (write_fw && isQ == 0) {
        u64t* fw = (u64t*)(out_fw + ((size_t)chain * DH + r) * DH + g * 8);
#pragma unroll
        for (int j = 0; j < 4; j++) fw[j] = Wp[j];
    }
}

// ---------------------------------------------------------------------------
extern "C" void kernel_launch(void* const* d_in, const int* in_sizes, int n_in,
                              void* d_out, int out_size)
{
    const float* x        = (const float*)d_in[0];
    const float* state    = (const float*)d_in[1];
    const float* W_slow   = (const float*)d_in[2];
    const float* ln_gamma = (const float*)d_in[3];
    const float* ln_beta  = (const float*)d_in[4];
    const float* W_out    = (const float*)d_in[5];
    float* out = (float*)d_out;

    float* normed; cudaGetSymbolAddress((void**)&normed, g_normed);
    float* qkvb;   cudaGetSymbolAddress((void**)&qkvb,   g_qkvb);
    float* oseq;   cudaGetSymbolAddress((void**)&oseq,   g_oseq);
    float* wslow;  cudaGetSymbolAddress((void**)&wslow,  g_wslow_t);
    float* wout;   cudaGetSymbolAddress((void**)&wout,   g_wout_t);

    // allow rec_kernel's 86.5KB dynamic smem (idempotent; no allocation)
    cudaFuncSetAttribute(rec_kernel,
                         cudaFuncAttributeMaxDynamicSharedMemorySize,
                         (int)sizeof(RecSmem));

    // 0) LN (warp/row, tf32 out) + weight rounding
    ln_round_kernel<<<NTOK / 8 + RTOT / 256, 256>>>(x, ln_gamma, ln_beta, W_slow, W_out);

    // 1) qkvb = normed @ W_slow^T   [16384 x 776], tf32 TC + cp.async
    dim3 gB(NTOK / TBM, (PROJ + TBN - 1) / TBN);
    gemm_tf32<<<gB, 128>>>(normed, wslow, qkvb, NTOK, PROJ, IND, nullptr);

    // 2) fused prep (8-step WY chunks)
    prep_fused<<<NCHAIN * NCH8 / 4, 128>>>();

    // 3) delta-rule recurrence (2 chains/block, 512 thr) — ncu idx 3
    int write_fw = (out_size >= (int)((size_t)NTOK * IND + FW_ELEMS)) ? 1 : 0;
    rec_kernel<<<NCHAIN / 2, 512, sizeof(RecSmem)>>>(state, out + (size_t)NTOK * IND, write_fw);

    // 4) out = x + oseq @ W_out^T   [16384 x 256], tf32 TC (resid fp32)
    dim3 gD(NTOK / TBM, (IND + TBN - 1) / TBN);
    gemm_tf32<<<gD, 128>>>(oseq, wout, out, NTOK, IND, IND, x);
}

// round 15
// speedup vs baseline: 1.0834x; 1.0834x over previous
#include <cuda_runtime.h>
#include <cstdint>

#define SLEN 1024
#define BSZ  16
#define IND  256
#define NH   8
#define DH   32
#define PROJ 776              // NH*(3*DH+1)
#define NTOK (SLEN*BSZ)       // 16384
#define NCHAIN (BSZ*NH)       // 128
#define FW_ELEMS (NCHAIN*DH*DH)
#define TCH  32               // staged steps per refill (4 chunks of 8)
#define CH8  8                // WY chunk size
#define NCH8 (SLEN/CH8)       // 128 chunks per chain
#define RTOT (PROJ*IND + IND*IND)   // 264192 weight elems to round

// Scratch (static device globals; no runtime allocation)
__device__ __align__(16) float g_normed[(size_t)NTOK*IND];   // tf32-rounded
__device__ __align__(16) float g_qkvb[(size_t)NTOK*PROJ];
__device__ __align__(16) float g_oseq[(size_t)NTOK*IND];     // tf32-rounded
__device__ __align__(16) float g_kn[(size_t)NCHAIN*SLEN*DH];
__device__ __align__(16) float g_qn[(size_t)NCHAIN*SLEN*DH];
__device__ __align__(16) float g_bv[(size_t)NCHAIN*SLEN*DH];  // beta*v
__device__ __align__(16) float g_nb[(size_t)NCHAIN*SLEN];     // -beta
__device__ __align__(16) float g_cross[(size_t)NCHAIN*NCH8*64];
__device__ __align__(16) float g_wslow_t[(size_t)PROJ*IND];  // tf32-rounded
__device__ __align__(16) float g_wout_t[(size_t)IND*IND];    // tf32-rounded

// ---------------------------------------------------------------------------
// helpers
// ---------------------------------------------------------------------------
typedef unsigned long long u64t;

__device__ __forceinline__ u64t f2pack(float lo, float hi) {
    u64t r; asm("mov.b64 %0, {%1, %2};" : "=l"(r) : "f"(lo), "f"(hi)); return r;
}
__device__ __forceinline__ void f2unpack(u64t v, float& lo, float& hi) {
    asm("mov.b64 {%0, %1}, %2;" : "=f"(lo), "=f"(hi) : "l"(v));
}
__device__ __forceinline__ u64t ffma2(u64t a, u64t b, u64t c) {
    u64t d; asm("fma.rn.f32x2 %0, %1, %2, %3;" : "=l"(d) : "l"(a), "l"(b), "l"(c)); return d;
}
__device__ __forceinline__ uint32_t to_tf32(float x) {
    uint32_t u; asm("cvt.rna.tf32.f32 %0, %1;" : "=r"(u) : "f"(x)); return u;
}
__device__ __forceinline__ float rnd_tf32(float x) {
    return __uint_as_float(to_tf32(x));
}
__device__ __forceinline__ uint32_t smem_u32(const void* p) {
    return (uint32_t)__cvta_generic_to_shared(p);
}
__device__ __forceinline__ void cp16(uint32_t d, const void* s, int ssz) {
    asm volatile("cp.async.ca.shared.global [%0], [%1], 16, %2;" :: "r"(d), "l"(s), "r"(ssz));
}
__device__ __forceinline__ void cp_commit() { asm volatile("cp.async.commit_group;" ::); }
__device__ __forceinline__ void cp_wait0()  { asm volatile("cp.async.wait_group 0;" ::); }

// upper-tri (i<=j) and strict (i<j) index maps over 8 steps
__host__ __device__ constexpr int UTx(int i, int j) { return i * (15 - i) / 2 + j; }
__host__ __device__ constexpr int STx(int i, int j) { return i * (13 - i) / 2 + j - 1; }

// ---------------------------------------------------------------------------
// LN: one WARP per row (2x float4 per thread, shuffle-only) + weight rounding
// ---------------------------------------------------------------------------
__global__ __launch_bounds__(256)
void ln_round_kernel(const float* __restrict__ x,
                     const float* __restrict__ gamma,
                     const float* __restrict__ beta,
                     const float* __restrict__ Wslow,
                     const float* __restrict__ Wout)
{
    int blk = blockIdx.x, tid = threadIdx.x;
    if (blk >= NTOK / 8) {
        int i = (blk - NTOK / 8) * 256 + tid;
        if (i < PROJ * IND)       g_wslow_t[i] = rnd_tf32(Wslow[i]);
        else if (i < RTOT)        g_wout_t[i - PROJ * IND] = rnd_tf32(Wout[i - PROJ * IND]);
        return;
    }
    int wid = tid >> 5, lane = tid & 31;
    int row = blk * 8 + wid;
    const float4* xr = (const float4*)(x + (size_t)row * IND);
    float4 a = xr[lane * 2], b2 = xr[lane * 2 + 1];
    float s  = (a.x + a.y + a.z + a.w) + (b2.x + b2.y + b2.z + b2.w);
    float s2 = (a.x*a.x + a.y*a.y + a.z*a.z + a.w*a.w) +
               (b2.x*b2.x + b2.y*b2.y + b2.z*b2.z + b2.w*b2.w);
#pragma unroll
    for (int o = 16; o > 0; o >>= 1) {
        s  += __shfl_xor_sync(0xffffffffu, s,  o);
        s2 += __shfl_xor_sync(0xffffffffu, s2, o);
    }
    float mu  = s * (1.0f / IND);
    float var = s2 * (1.0f / IND) - mu * mu;
    float rr  = rsqrtf(var + 1e-5f);
    float4 ga = ((const float4*)gamma)[lane * 2], gb = ((const float4*)gamma)[lane * 2 + 1];
    float4 ba = ((const float4*)beta)[lane * 2],  bb = ((const float4*)beta)[lane * 2 + 1];
    float4 o0, o1;
    o0.x = rnd_tf32((a.x - mu) * rr * ga.x + ba.x);
    o0.y = rnd_tf32((a.y - mu) * rr * ga.y + ba.y);
    o0.z = rnd_tf32((a.z - mu) * rr * ga.z + ba.z);
    o0.w = rnd_tf32((a.w - mu) * rr * ga.w + ba.w);
    o1.x = rnd_tf32((b2.x - mu) * rr * gb.x + bb.x);
    o1.y = rnd_tf32((b2.y - mu) * rr * gb.y + bb.y);
    o1.z = rnd_tf32((b2.z - mu) * rr * gb.z + bb.z);
    o1.w = rnd_tf32((b2.w - mu) * rr * gb.w + bb.w);
    float4* orow = (float4*)(g_normed + (size_t)row * IND);
    orow[lane * 2]     = o0;
    orow[lane * 2 + 1] = o1;
}

// ---------------------------------------------------------------------------
// TF32 tensor-core GEMM, cp.async streamed. Block 128x128, 4 warps (2x2),
// warp tile 64x64 (mf=4, nf=8) -> 128 smem-bytes per MMA.
// ---------------------------------------------------------------------------
#define TBM 128
#define TBN 128
#define TBK 16
#define TPAD 20

__global__ __launch_bounds__(128)
void gemm_tf32(const float* __restrict__ A, const float* __restrict__ B,
               float* __restrict__ C, int M, int N, int K,
               const float* __restrict__ resid)
{
    __shared__ uint32_t As[2][TBM][TPAD];
    __shared__ uint32_t Bs[2][TBN][TPAD];

    int bm = blockIdx.x * TBM;
    int bn = blockIdx.y * TBN;
    int tid = threadIdx.x;
    int wid = tid >> 5, lane = tid & 31;
    int warpM = wid & 1, warpN = wid >> 1;        // 2 x 2 warp grid
    int gID = lane >> 2, tIG = lane & 3;
    int wm0 = warpM * 64, wn0 = warpN * 64;

    // staging: 4 cp16 per operand per thread
    int rr[4], kc[4], bz[4];
    uint32_t aA[2][4], aB[2][4];
#pragma unroll
    for (int i = 0; i < 4; i++) {
        int f = tid + i * 128;
        rr[i] = f >> 2; kc[i] = (f & 3) * 4;
        bz[i] = (bn + rr[i] < N) ? 16 : 0;
#pragma unroll
        for (int bf = 0; bf < 2; bf++) {
            aA[bf][i] = smem_u32(&As[bf][rr[i]][kc[i]]);
            aB[bf][i] = smem_u32(&Bs[bf][rr[i]][kc[i]]);
        }
    }

    auto LOADA = [&](int k0, int bf) {
#pragma unroll
        for (int i = 0; i < 4; i++) {
            cp16(aA[bf][i], A + (size_t)(bm + rr[i]) * K + k0 + kc[i], 16);
            cp16(aB[bf][i], B + (size_t)(bn + rr[i]) * K + k0 + kc[i], bz[i]);
        }
        cp_commit();
    };

    float acc[4][8][4];
#pragma unroll
    for (int i = 0; i < 4; i++)
#pragma unroll
        for (int j = 0; j < 8; j++)
#pragma unroll
            for (int c = 0; c < 4; c++) acc[i][j][c] = 0.f;

    LOADA(0, 0);

    int nk = K / TBK;
    for (int kt = 0; kt < nk; kt++) {
        int cur = kt & 1;
        cp_wait0();
        __syncthreads();
        if (kt + 1 < nk) LOADA((kt + 1) * TBK, cur ^ 1);

#pragma unroll
        for (int k8 = 0; k8 < TBK; k8 += 8) {
            uint32_t af[4][4];
#pragma unroll
            for (int mf = 0; mf < 4; mf++) {
                int row = wm0 + mf * 16 + gID;
                af[mf][0] = As[cur][row][k8 + tIG];
                af[mf][1] = As[cur][row + 8][k8 + tIG];
                af[mf][2] = As[cur][row][k8 + tIG + 4];
                af[mf][3] = As[cur][row + 8][k8 + tIG + 4];
            }
#pragma unroll
            for (int nf = 0; nf < 8; nf++) {
                int col = wn0 + nf * 8 + gID;
                uint32_t b0 = Bs[cur][col][k8 + tIG];
                uint32_t b1 = Bs[cur][col][k8 + tIG + 4];
#pragma unroll
                for (int mf = 0; mf < 4; mf++) {
                    asm volatile(
                        "mma.sync.aligned.m16n8k8.row.col.f32.tf32.tf32.f32 "
                        "{%0,%1,%2,%3}, {%4,%5,%6,%7}, {%8,%9}, {%0,%1,%2,%3};"
                        : "+f"(acc[mf][nf][0]), "+f"(acc[mf][nf][1]),
                          "+f"(acc[mf][nf][2]), "+f"(acc[mf][nf][3])
                        : "r"(af[mf][0]), "r"(af[mf][1]), "r"(af[mf][2]), "r"(af[mf][3]),
                          "r"(b0), "r"(b1));
                }
            }
        }
    }

#pragma unroll
    for (int mf = 0; mf < 4; mf++) {
#pragma unroll
        for (int nf = 0; nf < 8; nf++) {
            int m = bm + wm0 + mf * 16 + gID;
            int n = bn + wn0 + nf * 8 + 2 * tIG;
            if (n < N) {
                float c0 = acc[mf][nf][0], c1 = acc[mf][nf][1];
                float c2 = acc[mf][nf][2], c3 = acc[mf][nf][3];
                if (resid) {
                    float2 ra = *(const float2*)(resid + (size_t)m * N + n);
                    float2 rb = *(const float2*)(resid + (size_t)(m + 8) * N + n);
                    c0 += ra.x; c1 += ra.y; c2 += rb.x; c3 += rb.y;
                }
                *(float2*)(C + (size_t)m * N + n)       = make_float2(c0, c1);
                *(float2*)(C + (size_t)(m + 8) * N + n) = make_float2(c2, c3);
            }
        }
    }
}

// ---------------------------------------------------------------------------
// Fused prep, 8-step chunks: one warp per (chain, chunk).
// Streams out: kn, qn (normalized), bv = beta*v, nb = -beta, cross terms.
// cross layout per chunk: [0..35] kq(i<=j), [36..63] -b_j*kk(i<j)
// ---------------------------------------------------------------------------
__global__ __launch_bounds__(128)
void prep_fused()
{
    int gw   = blockIdx.x * 4 + (threadIdx.x >> 5);   // 0 .. NCHAIN*NCH8-1
    int lane = threadIdx.x & 31;
    int ch   = gw >> 7;          // chain  (NCH8 = 128)
    int cu   = gw & 127;         // chunk
    int t0   = cu * CH8;
    int b    = ch >> 3, h = ch & 7;

    float eq[8], ek[8], vv[8], be[8];
#pragma unroll
    for (int s = 0; s < 8; s++) {
        const float* base = g_qkvb + ((size_t)(t0 + s) * BSZ + b) * PROJ + h * 97;
        float q = base[lane], k = base[32 + lane];
        vv[s]  = base[64 + lane];
        be[s]  = 1.0f / (1.0f + __expf(-base[96]));
        eq[s] = q > 0.f ? q + 1.f : __expf(q);
        ek[s] = k > 0.f ? k + 1.f : __expf(k);
    }

    float r[80];
#pragma unroll
    for (int s = 0; s < 8; s++) { r[s] = eq[s]; r[8 + s] = ek[s]; }
#pragma unroll
    for (int i = 0; i < 8; i++)
#pragma unroll
        for (int j = 0; j < 8; j++)
            if (j >= i) r[16 + UTx(i, j)] = ek[i] * eq[j];
#pragma unroll
    for (int i = 0; i < 8; i++)
#pragma unroll
        for (int j = 0; j < 8; j++)
            if (j > i) r[52 + STx(i, j)] = ek[i] * ek[j];

#pragma unroll
    for (int o = 16; o > 0; o >>= 1) {
#pragma unroll
        for (int i = 0; i < 80; i++)
            r[i] += __shfl_xor_sync(0xffffffffu, r[i], o);
    }

    float rsq[8], rsk[8];
#pragma unroll
    for (int s = 0; s < 8; s++) {
        rsq[s] = 1.0f / (r[s] + 1e-5f);
        rsk[s] = 1.0f / (r[8 + s] + 1e-5f);
    }

#pragma unroll
    for (int s = 0; s < 8; s++) {
        size_t oi = ((size_t)ch * SLEN + t0 + s) * DH + lane;
        g_qn[oi] = eq[s] * rsq[s];
        g_kn[oi] = ek[s] * rsk[s];
        g_bv[oi] = be[s] * vv[s];
    }

#pragma unroll
    for (int i = 0; i < 8; i++)
#pragma unroll
        for (int j = 0; j < 8; j++)
            if (j >= i) r[16 + UTx(i, j)] *= rsk[i] * rsq[j];
#pragma unroll
    for (int i = 0; i < 8; i++)
#pragma unroll
        for (int j = 0; j < 8; j++)
            if (j > i) r[52 + STx(i, j)] *= -be[j] * rsk[i] * rsk[j];

    if (lane == 0) {
        size_t bb = (size_t)ch * SLEN + t0;
#pragma unroll
        for (int s = 0; s < 8; s++) g_nb[bb + s] = -be[s];
        float4* o = (float4*)(g_cross + ((size_t)ch * NCH8 + cu) * 64);
#pragma unroll
        for (int u = 0; u < 16; u++)
            o[u] = make_float4(r[16 + 4 * u], r[17 + 4 * u], r[18 + 4 * u], r[19 + 4 * u]);
    }
}

// ---------------------------------------------------------------------------
// Delta-rule recurrence (PROVEN R10 version): 1 chain per 256-thread block,
// WY chunk = 8, 8 warps. Warp w: col-group g = w&3, role = w>>2.
// LDS.128 everywhere; role-k keeps k-slices in regs; one barrier per chunk.
// ---------------------------------------------------------------------------
__global__ __launch_bounds__(256)
void rec_kernel(const float* __restrict__ state,
                float* __restrict__ out_fw, int write_fw)
{
    int chain = blockIdx.x;            // 0..127
    int b = chain >> 3, h = chain & 7;
    int tid = threadIdx.x;
    int r = tid & 31;                  // row
    int w = tid >> 5;                  // warp 0..7
    int g = w & 3;                     // column group
    int isQ = w >> 2;                  // role

    u64t Wp[4];
    const u64t* st = (const u64t*)(state + ((size_t)chain * DH + r) * DH + g * 8);
#pragma unroll
    for (int j = 0; j < 4; j++) Wp[j] = st[j];

    __shared__ __align__(16) float sk[2][TCH * DH];
    __shared__ __align__(16) float sq[2][TCH * DH];
    __shared__ __align__(16) float sbv[2][TCH * DH];
    __shared__ float snb[2][TCH];
    __shared__ __align__(16) float scr[2][256];          // 4 chunks x 64
    __shared__ __align__(16) float part[2][16][32][4];   // [pc][s][row][g]

    const float* kb  = g_kn + (size_t)chain * SLEN * DH;
    const float* qb  = g_qn + (size_t)chain * SLEN * DH;
    const float* vb  = g_bv + (size_t)chain * SLEN * DH;
    const float* nbb = g_nb + (size_t)chain * SLEN;
    const float* crb = g_cross + (size_t)chain * NCH8 * 64;

    auto REFILL = [&](int cc, int buf) {
        ((float4*)sk[buf])[tid]  = ((const float4*)(kb + (size_t)cc * TCH * DH))[tid];
        ((float4*)sq[buf])[tid]  = ((const float4*)(qb + (size_t)cc * TCH * DH))[tid];
        ((float4*)sbv[buf])[tid] = ((const float4*)(vb + (size_t)cc * TCH * DH))[tid];
        if (tid < TCH) snb[buf][tid] = nbb[cc * TCH + tid];
        scr[buf][tid] = crb[(size_t)cc * 256 + tid];
    };

    REFILL(0, 0);
    __syncthreads();

    const int NCC = SLEN / TCH;     // 32 refills, 4 chunks each
    for (int cc = 0; cc < NCC; cc++) {
        int buf = cc & 1;
        if (cc + 1 < NCC) REFILL(cc + 1, buf ^ 1);

#pragma unroll
        for (int sub = 0; sub < TCH / CH8; sub++) {
            int tb = sub * CH8;
            int pc = sub & 1;

            const float* srcb = isQ ? &sq[buf][0] : &sk[buf][0];
            u64t ks[8][4];
#pragma unroll
            for (int s = 0; s < 8; s++) {
                const float4* vp4 = (const float4*)&srcb[(tb + s) * DH + g * 8];
                float4 t0 = vp4[0], t1 = vp4[1];
                u64t v0 = f2pack(t0.x, t0.y), v1 = f2pack(t0.z, t0.w);
                u64t v2 = f2pack(t1.x, t1.y), v3 = f2pack(t1.z, t1.w);
                if (!isQ) { ks[s][0] = v0; ks[s][1] = v1; ks[s][2] = v2; ks[s][3] = v3; }
                u64t aa = ffma2(Wp[0], v0, 0ull), bb2 = ffma2(Wp[1], v1, 0ull);
                aa = ffma2(Wp[2], v2, aa); bb2 = ffma2(Wp[3], v3, bb2);
                float x0, x1, y0, y1;
                f2unpack(aa, x0, x1); f2unpack(bb2, y0, y1);
                part[pc][isQ * 8 + s][r][g] = (x0 + y0) + (x1 + y1);
            }
            __syncthreads();

            float A[8];
#pragma unroll
            for (int s = 0; s < 8; s++) {
                float4 pa = *(const float4*)part[pc][s][r];
                A[s] = (pa.x + pa.y) + (pa.z + pa.w);
            }

            const float* cq = &scr[buf][sub * 64];
            const float* ck = cq + 36;

            float acc[8];
#pragma unroll
            for (int j = 0; j < 8; j++)
                acc[j] = fmaf(snb[buf][tb + j], A[j], sbv[buf][(tb + j) * DH + r]);
            float d[8];
#pragma unroll
            for (int i = 0; i < 8; i++) {
                d[i] = acc[i];
#pragma unroll
                for (int j = 0; j < 8; j++)
                    if (j > i) acc[j] = fmaf(d[i], ck[STx(i, j)], acc[j]);
            }

            // output: warp w emits step w
            float4 pq = *(const float4*)part[pc][8 + w][r];
            float Qw = (pq.x + pq.y) + (pq.z + pq.w);
#pragma unroll
            for (int i = 0; i < 8; i++)
                if (i <= w) Qw = fmaf(d[i], cq[UTx(i, w)], Qw);
            int tg = cc * TCH + tb;
            g_oseq[((size_t)(tg + w) * BSZ + b) * IND + h * DH + r] = rnd_tf32(Qw);

            // rank-8 update
            if (!isQ) {
#pragma unroll
                for (int s = 0; s < 8; s++) {
                    u64t D = f2pack(d[s], d[s]);
#pragma unroll
                    for (int j = 0; j < 4; j++) Wp[j] = ffma2(D, ks[s][j], Wp[j]);
                }
            } else {
#pragma unroll
                for (int s = 0; s < 8; s++) {
                    const float4* kp4 = (const float4*)&sk[buf][(tb + s) * DH + g * 8];
                    float4 t0 = kp4[0], t1 = kp4[1];
                    u64t D = f2pack(d[s], d[s]);
                    Wp[0] = ffma2(D, f2pack(t0.x, t0.y), Wp[0]);
                    Wp[1] = ffma2(D, f2pack(t0.z, t0.w), Wp[1]);
                    Wp[2] = ffma2(D, f2pack(t1.x, t1.y), Wp[2]);
                    Wp[3] = ffma2(D, f2pack(t1.z, t1.w), Wp[3]);
                }
            }
        }
        __syncthreads();   // close refill window for buf
    }

    if (write_fw && isQ == 0) {
        u64t* fw = (u64t*)(out_fw + ((size_t)chain * DH + r) * DH + g * 8);
#pragma unroll
        for (int j = 0; j < 4; j++) fw[j] = Wp[j];
    }
}

// ---------------------------------------------------------------------------
extern "C" void kernel_launch(void* const* d_in, const int* in_sizes, int n_in,
                              void* d_out, int out_size)
{
    const float* x        = (const float*)d_in[0];
    const float* state    = (const float*)d_in[1];
    const float* W_slow   = (const float*)d_in[2];
    const float* ln_gamma = (const float*)d_in[3];
    const float* ln_beta  = (const float*)d_in[4];
    const float* W_out    = (const float*)d_in[5];
    float* out = (float*)d_out;

    float* normed; cudaGetSymbolAddress((void**)&normed, g_normed);
    float* qkvb;   cudaGetSymbolAddress((void**)&qkvb,   g_qkvb);
    float* oseq;   cudaGetSymbolAddress((void**)&oseq,   g_oseq);
    float* wslow;  cudaGetSymbolAddress((void**)&wslow,  g_wslow_t);
    float* wout;   cudaGetSymbolAddress((void**)&wout,   g_wout_t);

    // 0) LN (warp/row, tf32 out) + weight rounding
    ln_round_kernel<<<NTOK / 8 + RTOT / 256, 256>>>(x, ln_gamma, ln_beta, W_slow, W_out);

    // 1) qkvb = normed @ W_slow^T   [16384 x 776], tf32 TC + cp.async
    dim3 gB(NTOK / TBM, (PROJ + TBN - 1) / TBN);
    gemm_tf32<<<gB, 128>>>(normed, wslow, qkvb, NTOK, PROJ, IND, nullptr);

    // 2) fused prep (8-step WY chunks)
    prep_fused<<<NCHAIN * NCH8 / 4, 128>>>();

    // 3) delta-rule recurrence (R10 proven version: 1 chain / 256-thr block)
    int write_fw = (out_size >= (int)((size_t)NTOK * IND + FW_ELEMS)) ? 1 : 0;
    rec_kernel<<<NCHAIN, 256>>>(state, out + (size_t)NTOK * IND, write_fw);

    // 4) out = x + oseq @ W_out^T   [16384 x 256], tf32 TC (resid fp32)
    dim3 gD(NTOK / TBM, (IND + TBN - 1) / TBN);
    gemm_tf32<<<gD, 128>>>(oseq, wout, out, NTOK, IND, IND, x);
}

// round 16
// speedup vs baseline: 1.6199x; 1.4952x over previous
#include <cuda_runtime.h>
#include <cstdint>

#define SLEN 1024
#define BSZ  16
#define IND  256
#define NH   8
#define DH   32
#define PROJ 776              // NH*(3*DH+1)
#define NTOK (SLEN*BSZ)       // 16384
#define NCHAIN (BSZ*NH)       // 128
#define FW_ELEMS (NCHAIN*DH*DH)
#define TCH  32               // staged steps per refill (4 chunks of 8)
#define CH8  8                // WY chunk size
#define NCH8 (SLEN/CH8)       // 128 chunks per chain
#define RTOT (PROJ*IND + IND*IND)   // 264192 weight elems to round

// Scratch (static device globals; no runtime allocation)
__device__ __align__(16) float g_normed[(size_t)NTOK*IND];   // tf32-rounded
__device__ __align__(16) float g_qkvb[(size_t)NTOK*PROJ];
__device__ __align__(16) float g_oseq[(size_t)NTOK*IND];     // tf32-rounded
__device__ __align__(16) float g_kn[(size_t)NCHAIN*SLEN*DH];
__device__ __align__(16) float g_qn[(size_t)NCHAIN*SLEN*DH];
__device__ __align__(16) float g_vn[(size_t)NCHAIN*SLEN*DH];
__device__ __align__(16) float g_beta[(size_t)NCHAIN*SLEN];
__device__ __align__(16) float g_cross[(size_t)NCHAIN*NCH8*64];
__device__ __align__(16) float g_wslow_t[(size_t)PROJ*IND];  // tf32-rounded
__device__ __align__(16) float g_wout_t[(size_t)IND*IND];    // tf32-rounded

// ---------------------------------------------------------------------------
// helpers
// ---------------------------------------------------------------------------
typedef unsigned long long u64t;

__device__ __forceinline__ u64t f2pack(float lo, float hi) {
    u64t r; asm("mov.b64 %0, {%1, %2};" : "=l"(r) : "f"(lo), "f"(hi)); return r;
}
__device__ __forceinline__ void f2unpack(u64t v, float& lo, float& hi) {
    asm("mov.b64 {%0, %1}, %2;" : "=f"(lo), "=f"(hi) : "l"(v));
}
__device__ __forceinline__ u64t ffma2(u64t a, u64t b, u64t c) {
    u64t d; asm("fma.rn.f32x2 %0, %1, %2, %3;" : "=l"(d) : "l"(a), "l"(b), "l"(c)); return d;
}
__device__ __forceinline__ uint32_t to_tf32(float x) {
    uint32_t u; asm("cvt.rna.tf32.f32 %0, %1;" : "=r"(u) : "f"(x)); return u;
}
__device__ __forceinline__ float rnd_tf32(float x) {
    return __uint_as_float(to_tf32(x));
}
__device__ __forceinline__ uint32_t smem_u32(const void* p) {
    return (uint32_t)__cvta_generic_to_shared(p);
}
__device__ __forceinline__ void cp16(uint32_t d, const void* s, int ssz) {
    asm volatile("cp.async.ca.shared.global [%0], [%1], 16, %2;" :: "r"(d), "l"(s), "r"(ssz));
}
__device__ __forceinline__ void cp_commit() { asm volatile("cp.async.commit_group;" ::); }
__device__ __forceinline__ void cp_wait0()  { asm volatile("cp.async.wait_group 0;" ::); }

// 8-wide dot of packed slices (4 x f32x2)
__device__ __forceinline__ float dot8(const u64t* __restrict__ Wp,
                                      const u64t* __restrict__ vp) {
    u64t a = 0ull, b = 0ull;
    a = ffma2(Wp[0], vp[0], a); b = ffma2(Wp[1], vp[1], b);
    a = ffma2(Wp[2], vp[2], a); b = ffma2(Wp[3], vp[3], b);
    float x0, x1, y0, y1;
    f2unpack(a, x0, x1); f2unpack(b, y0, y1);
    return (x0 + y0) + (x1 + y1);
}

// upper-tri (i<=j) and strict (i<j) index maps over 8 steps
__host__ __device__ constexpr int UTx(int i, int j) { return i * (15 - i) / 2 + j; }
__host__ __device__ constexpr int STx(int i, int j) { return i * (13 - i) / 2 + j - 1; }

// ---------------------------------------------------------------------------
// LN: one WARP per row (2x float4 per thread, shuffle-only) + weight rounding
// ---------------------------------------------------------------------------
__global__ __launch_bounds__(256)
void ln_round_kernel(const float* __restrict__ x,
                     const float* __restrict__ gamma,
                     const float* __restrict__ beta,
                     const float* __restrict__ Wslow,
                     const float* __restrict__ Wout)
{
    int blk = blockIdx.x, tid = threadIdx.x;
    if (blk >= NTOK / 8) {
        int i = (blk - NTOK / 8) * 256 + tid;
        if (i < PROJ * IND)       g_wslow_t[i] = rnd_tf32(Wslow[i]);
        else if (i < RTOT)        g_wout_t[i - PROJ * IND] = rnd_tf32(Wout[i - PROJ * IND]);
        return;
    }
    int wid = tid >> 5, lane = tid & 31;
    int row = blk * 8 + wid;
    const float4* xr = (const float4*)(x + (size_t)row * IND);
    float4 a = xr[lane * 2], b2 = xr[lane * 2 + 1];
    float s  = (a.x + a.y + a.z + a.w) + (b2.x + b2.y + b2.z + b2.w);
    float s2 = (a.x*a.x + a.y*a.y + a.z*a.z + a.w*a.w) +
               (b2.x*b2.x + b2.y*b2.y + b2.z*b2.z + b2.w*b2.w);
#pragma unroll
    for (int o = 16; o > 0; o >>= 1) {
        s  += __shfl_xor_sync(0xffffffffu, s,  o);
        s2 += __shfl_xor_sync(0xffffffffu, s2, o);
    }
    float mu  = s * (1.0f / IND);
    float var = s2 * (1.0f / IND) - mu * mu;
    float rr  = rsqrtf(var + 1e-5f);
    float4 ga = ((const float4*)gamma)[lane * 2], gb = ((const float4*)gamma)[lane * 2 + 1];
    float4 ba = ((const float4*)beta)[lane * 2],  bb = ((const float4*)beta)[lane * 2 + 1];
    float4 o0, o1;
    o0.x = rnd_tf32((a.x - mu) * rr * ga.x + ba.x);
    o0.y = rnd_tf32((a.y - mu) * rr * ga.y + ba.y);
    o0.z = rnd_tf32((a.z - mu) * rr * ga.z + ba.z);
    o0.w = rnd_tf32((a.w - mu) * rr * ga.w + ba.w);
    o1.x = rnd_tf32((b2.x - mu) * rr * gb.x + bb.x);
    o1.y = rnd_tf32((b2.y - mu) * rr * gb.y + bb.y);
    o1.z = rnd_tf32((b2.z - mu) * rr * gb.z + bb.z);
    o1.w = rnd_tf32((b2.w - mu) * rr * gb.w + bb.w);
    float4* orow = (float4*)(g_normed + (size_t)row * IND);
    orow[lane * 2]     = o0;
    orow[lane * 2 + 1] = o1;
}

// ---------------------------------------------------------------------------
// TF32 tensor-core GEMM, cp.async streamed (operands pre-rounded to tf32):
// PROVEN R10 config: block 128x128, BK=16, 8 warps (4x2), warp tile 32x64.
// ---------------------------------------------------------------------------
#define TBM 128
#define TBN 128
#define TBK 16
#define TPAD 20

__global__ __launch_bounds__(256)
void gemm_tf32(const float* __restrict__ A, const float* __restrict__ B,
               float* __restrict__ C, int M, int N, int K,
               const float* __restrict__ resid)
{
    __shared__ uint32_t As[2][TBM][TPAD];
    __shared__ uint32_t Bs[2][TBN][TPAD];

    int bm = blockIdx.x * TBM;
    int bn = blockIdx.y * TBN;
    int tid = threadIdx.x;
    int wid = tid >> 5, lane = tid & 31;
    int warpM = wid & 3, warpN = wid >> 2;        // 4 x 2 warp grid
    int gID = lane >> 2, tIG = lane & 3;
    int wm0 = warpM * 32, wn0 = warpN * 64;

    int f0 = tid,       r0 = f0 >> 2, kc0 = (f0 & 3) * 4;
    int f1 = tid + 256, r1 = f1 >> 2, kc1 = (f1 & 3) * 4;

    uint32_t aA[2], aA1[2], aB[2], aB1[2];
#pragma unroll
    for (int bf = 0; bf < 2; bf++) {
        aA[bf]  = smem_u32(&As[bf][r0][kc0]);
        aA1[bf] = smem_u32(&As[bf][r1][kc1]);
        aB[bf]  = smem_u32(&Bs[bf][r0][kc0]);
        aB1[bf] = smem_u32(&Bs[bf][r1][kc1]);
    }
    int bz0 = (bn + r0 < N) ? 16 : 0;
    int bz1 = (bn + r1 < N) ? 16 : 0;

    auto LOADA = [&](int k0, int bf) {
        cp16(aA[bf],  A + (size_t)(bm + r0) * K + k0 + kc0, 16);
        cp16(aA1[bf], A + (size_t)(bm + r1) * K + k0 + kc1, 16);
        cp16(aB[bf],  B + (size_t)(bn + r0) * K + k0 + kc0, bz0);
        cp16(aB1[bf], B + (size_t)(bn + r1) * K + k0 + kc1, bz1);
        cp_commit();
    };

    float acc[2][8][4];
#pragma unroll
    for (int i = 0; i < 2; i++)
#pragma unroll
        for (int j = 0; j < 8; j++)
#pragma unroll
            for (int c = 0; c < 4; c++) acc[i][j][c] = 0.f;

    LOADA(0, 0);

    int nk = K / TBK;
    for (int kt = 0; kt < nk; kt++) {
        int cur = kt & 1;
        cp_wait0();
        __syncthreads();
        if (kt + 1 < nk) LOADA((kt + 1) * TBK, cur ^ 1);

#pragma unroll
        for (int k8 = 0; k8 < TBK; k8 += 8) {
            uint32_t af[2][4];
#pragma unroll
            for (int mf = 0; mf < 2; mf++) {
                int row = wm0 + mf * 16 + gID;
                af[mf][0] = As[cur][row][k8 + tIG];
                af[mf][1] = As[cur][row + 8][k8 + tIG];
                af[mf][2] = As[cur][row][k8 + tIG + 4];
                af[mf][3] = As[cur][row + 8][k8 + tIG + 4];
            }
#pragma unroll
            for (int nf = 0; nf < 8; nf++) {
                int col = wn0 + nf * 8 + gID;
                uint32_t b0 = Bs[cur][col][k8 + tIG];
                uint32_t b1 = Bs[cur][col][k8 + tIG + 4];
#pragma unroll
                for (int mf = 0; mf < 2; mf++) {
                    asm volatile(
                        "mma.sync.aligned.m16n8k8.row.col.f32.tf32.tf32.f32 "
                        "{%0,%1,%2,%3}, {%4,%5,%6,%7}, {%8,%9}, {%0,%1,%2,%3};"
                        : "+f"(acc[mf][nf][0]), "+f"(acc[mf][nf][1]),
                          "+f"(acc[mf][nf][2]), "+f"(acc[mf][nf][3])
                        : "r"(af[mf][0]), "r"(af[mf][1]), "r"(af[mf][2]), "r"(af[mf][3]),
                          "r"(b0), "r"(b1));
                }
            }
        }
    }

#pragma unroll
    for (int mf = 0; mf < 2; mf++) {
#pragma unroll
        for (int nf = 0; nf < 8; nf++) {
            int m = bm + wm0 + mf * 16 + gID;
            int n = bn + wn0 + nf * 8 + 2 * tIG;
            if (n < N) {
                float c0 = acc[mf][nf][0], c1 = acc[mf][nf][1];
                float c2 = acc[mf][nf][2], c3 = acc[mf][nf][3];
                if (resid) {
                    float2 ra = *(const float2*)(resid + (size_t)m * N + n);
                    float2 rb = *(const float2*)(resid + (size_t)(m + 8) * N + n);
                    c0 += ra.x; c1 += ra.y; c2 += rb.x; c3 += rb.y;
                }
                *(float2*)(C + (size_t)m * N + n)       = make_float2(c0, c1);
                *(float2*)(C + (size_t)(m + 8) * N + n) = make_float2(c2, c3);
            }
        }
    }
}

// ---------------------------------------------------------------------------
// Fused prep, 8-step chunks: one warp per (chain, chunk).
// cross layout per chunk: [0..35] kq(i<=j), [36..63] -b_j*kk(i<j)
// ---------------------------------------------------------------------------
__global__ __launch_bounds__(128)
void prep_fused()
{
    int gw   = blockIdx.x * 4 + (threadIdx.x >> 5);   // 0 .. NCHAIN*NCH8-1
    int lane = threadIdx.x & 31;
    int ch   = gw >> 7;          // chain  (NCH8 = 128)
    int cu   = gw & 127;         // chunk
    int t0   = cu * CH8;
    int b    = ch >> 3, h = ch & 7;

    float eq[8], ek[8], vv[8], bta[8];
#pragma unroll
    for (int s = 0; s < 8; s++) {
        const float* base = g_qkvb + ((size_t)(t0 + s) * BSZ + b) * PROJ + h * 97;
        float q = base[lane], k = base[32 + lane];
        vv[s]  = base[64 + lane];
        bta[s] = base[96];
        eq[s] = q > 0.f ? q + 1.f : __expf(q);
        ek[s] = k > 0.f ? k + 1.f : __expf(k);
    }

    float r[80];
#pragma unroll
    for (int s = 0; s < 8; s++) { r[s] = eq[s]; r[8 + s] = ek[s]; }
#pragma unroll
    for (int i = 0; i < 8; i++)
#pragma unroll
        for (int j = 0; j < 8; j++)
            if (j >= i) r[16 + UTx(i, j)] = ek[i] * eq[j];
#pragma unroll
    for (int i = 0; i < 8; i++)
#pragma unroll
        for (int j = 0; j < 8; j++)
            if (j > i) r[52 + STx(i, j)] = ek[i] * ek[j];

#pragma unroll
    for (int o = 16; o > 0; o >>= 1) {
#pragma unroll
        for (int i = 0; i < 80; i++)
            r[i] += __shfl_xor_sync(0xffffffffu, r[i], o);
    }

    float rsq[8], rsk[8], be[8];
#pragma unroll
    for (int s = 0; s < 8; s++) {
        rsq[s] = 1.0f / (r[s] + 1e-5f);
        rsk[s] = 1.0f / (r[8 + s] + 1e-5f);
        be[s]  = 1.0f / (1.0f + __expf(-bta[s]));
    }

#pragma unroll
    for (int s = 0; s < 8; s++) {
        size_t oi = ((size_t)ch * SLEN + t0 + s) * DH + lane;
        g_qn[oi] = eq[s] * rsq[s];
        g_kn[oi] = ek[s] * rsk[s];
        g_vn[oi] = vv[s];
    }

#pragma unroll
    for (int i = 0; i < 8; i++)
#pragma unroll
        for (int j = 0; j < 8; j++)
            if (j >= i) r[16 + UTx(i, j)] *= rsk[i] * rsq[j];
#pragma unroll
    for (int i = 0; i < 8; i++)
#pragma unroll
        for (int j = 0; j < 8; j++)
            if (j > i) r[52 + STx(i, j)] *= -be[j] * rsk[i] * rsk[j];

    if (lane == 0) {
        size_t bb = (size_t)ch * SLEN + t0;
#pragma unroll
        for (int s = 0; s < 8; s++) g_beta[bb + s] = be[s];
        float4* o = (float4*)(g_cross + ((size_t)ch * NCH8 + cu) * 64);
#pragma unroll
        for (int u = 0; u < 16; u++)
            o[u] = make_float4(r[16 + 4 * u], r[17 + 4 * u], r[18 + 4 * u], r[19 + 4 * u]);
    }
}

// ---------------------------------------------------------------------------
// Delta-rule recurrence (PROVEN 266.9 version): WY chunk = 8, 8 warps/chain.
// Warp w: col-group g = w&3, role = w>>2 (0: k-dots, 1: q-dots). All warps
// redundantly run the scattered delta chain; warp w emits output step w.
// One barrier per 8-step chunk. regs=64 as compiled.
// ---------------------------------------------------------------------------
__global__ __launch_bounds__(256)
void rec_kernel(const float* __restrict__ state,
                float* __restrict__ out_fw, int write_fw)
{
    int chain = blockIdx.x;            // 0..127
    int b = chain >> 3, h = chain & 7;
    int tid = threadIdx.x;
    int r = tid & 31;                  // row
    int w = tid >> 5;                  // warp 0..7
    int g = w & 3;                     // column group
    int isQ = w >> 2;                  // role

    u64t Wp[4];
    const u64t* st = (const u64t*)(state + ((size_t)chain * DH + r) * DH + g * 8);
#pragma unroll
    for (int j = 0; j < 4; j++) Wp[j] = st[j];

    __shared__ __align__(16) float sk[2][TCH * DH];
    __shared__ __align__(16) float sq[2][TCH * DH];
    __shared__ __align__(16) float sv[2][TCH * DH];
    __shared__ float sbeta[2][TCH];
    __shared__ __align__(16) float scr[2][256];       // 4 chunks x 64
    __shared__ float part[2][16][32][5];              // [pc][s:0-7 A,8-15 Q][row][g]

    const float* kb  = g_kn   + (size_t)chain * SLEN * DH;
    const float* qb  = g_qn   + (size_t)chain * SLEN * DH;
    const float* vb  = g_vn   + (size_t)chain * SLEN * DH;
    const float* bb  = g_beta + (size_t)chain * SLEN;
    const float* crb = g_cross + (size_t)chain * NCH8 * 64;

    auto REFILL = [&](int cc, int buf) {
        ((float4*)sk[buf])[tid] = ((const float4*)(kb + (size_t)cc * TCH * DH))[tid];
        ((float4*)sq[buf])[tid] = ((const float4*)(qb + (size_t)cc * TCH * DH))[tid];
        ((float4*)sv[buf])[tid] = ((const float4*)(vb + (size_t)cc * TCH * DH))[tid];
        if (tid < TCH) sbeta[buf][tid] = bb[cc * TCH + tid];
        scr[buf][tid] = crb[(size_t)cc * 256 + tid];
    };

    REFILL(0, 0);
    __syncthreads();

    const int NCC = SLEN / TCH;     // 32 refills, 4 chunks each
    for (int cc = 0; cc < NCC; cc++) {
        int buf = cc & 1;
        if (cc + 1 < NCC) REFILL(cc + 1, buf ^ 1);

#pragma unroll
        for (int sub = 0; sub < TCH / CH8; sub++) {
            int tb = sub * CH8;
            int pc = sub & 1;

            // role-specialized dots: 8 per warp
            const float* src = isQ ? &sq[buf][0] : &sk[buf][0];
#pragma unroll
            for (int s = 0; s < 8; s++) {
                const u64t* vp = (const u64t*)&src[(tb + s) * DH + g * 8];
                part[pc][isQ * 8 + s][r][g] = dot8(Wp, vp);
            }
            __syncthreads();

            float A[8];
#pragma unroll
            for (int s = 0; s < 8; s++)
                A[s] = (part[pc][s][r][0] + part[pc][s][r][1]) +
                       (part[pc][s][r][2] + part[pc][s][r][3]);

            const float* cq = &scr[buf][sub * 64];
            const float* ck = cq + 36;

            // scattered-form forward substitution (serial depth = 8 fma)
            float acc[8];
#pragma unroll
            for (int j = 0; j < 8; j++) {
                float bej = sbeta[buf][tb + j];
                acc[j] = fmaf(-bej, A[j], bej * sv[buf][(tb + j) * DH + r]);
            }
            float d[8];
#pragma unroll
            for (int i = 0; i < 8; i++) {
                d[i] = acc[i];
#pragma unroll
                for (int j = 0; j < 8; j++)
                    if (j > i) acc[j] = fmaf(d[i], ck[STx(i, j)], acc[j]);
            }

            // output: warp w emits step w
            float Qw = (part[pc][8 + w][r][0] + part[pc][8 + w][r][1]) +
                       (part[pc][8 + w][r][2] + part[pc][8 + w][r][3]);
#pragma unroll
            for (int i = 0; i < 8; i++)
                if (i <= w) Qw = fmaf(d[i], cq[UTx(i, w)], Qw);
            int tg = cc * TCH + tb;
            g_oseq[((size_t)(tg + w) * BSZ + b) * IND + h * DH + r] = rnd_tf32(Qw);

            // rank-8 update on the local col-slice (both roles, identical)
#pragma unroll
            for (int s = 0; s < 8; s++) {
                const u64t* kp = (const u64t*)&sk[buf][(tb + s) * DH + g * 8];
                u64t D = f2pack(d[s], d[s]);
#pragma unroll
                for (int j = 0; j < 4; j++) Wp[j] = ffma2(D, kp[j], Wp[j]);
            }
        }
        __syncthreads();   // close refill window for buf
    }

    if (write_fw && isQ == 0) {
        u64t* fw = (u64t*)(out_fw + ((size_t)chain * DH + r) * DH + g * 8);
#pragma unroll
        for (int j = 0; j < 4; j++) fw[j] = Wp[j];
    }
}

// ---------------------------------------------------------------------------
extern "C" void kernel_launch(void* const* d_in, const int* in_sizes, int n_in,
                              void* d_out, int out_size)
{
    const float* x        = (const float*)d_in[0];
    const float* state    = (const float*)d_in[1];
    const float* W_slow   = (const float*)d_in[2];
    const float* ln_gamma = (const float*)d_in[3];
    const float* ln_beta  = (const float*)d_in[4];
    const float* W_out    = (const float*)d_in[5];
    float* out = (float*)d_out;

    float* normed; cudaGetSymbolAddress((void**)&normed, g_normed);
    float* qkvb;   cudaGetSymbolAddress((void**)&qkvb,   g_qkvb);
    float* oseq;   cudaGetSymbolAddress((void**)&oseq,   g_oseq);
    float* wslow;  cudaGetSymbolAddress((void**)&wslow,  g_wslow_t);
    float* wout;   cudaGetSymbolAddress((void**)&wout,   g_wout_t);

    // 0) LN (warp/row, tf32 out) + weight rounding
    ln_round_kernel<<<NTOK / 8 + RTOT / 256, 256>>>(x, ln_gamma, ln_beta, W_slow, W_out);

    // 1) qkvb = normed @ W_slow^T   [16384 x 776], tf32 TC + cp.async (256 thr)
    dim3 gB(NTOK / TBM, (PROJ + TBN - 1) / TBN);
    gemm_tf32<<<gB, 256>>>(normed, wslow, qkvb, NTOK, PROJ, IND, nullptr);

    // 2) fused prep (8-step WY chunks)
    prep_fused<<<NCHAIN * NCH8 / 4, 128>>>();

    // 3) delta-rule recurrence (proven 8-warp A/Q version)
    int write_fw = (out_size >= (int)((size_t)NTOK * IND + FW_ELEMS)) ? 1 : 0;
    rec_kernel<<<NCHAIN, 256>>>(state, out + (size_t)NTOK * IND, write_fw);

    // 4) out = x + oseq @ W_out^T   [16384 x 256], tf32 TC (resid fp32)
    dim3 gD(NTOK / TBM, (IND + TBN - 1) / TBN);
    gemm_tf32<<<gD, 256>>>(oseq, wout, out, NTOK, IND, IND, x);
}